// round 2
// baseline (speedup 1.0000x reference)
#include <cuda_runtime.h>
#include <cstdint>

// ============================================================================
// Problem constants
// ============================================================================
#define IN_DIM   4096
#define OUT_DIM  4096
#define M_ROWS   8192          // 4 * 2048
#define RANK     16
#define BLOCK_Q  64            // NF4 block size
#define LORA_SCALE 2.0f        // alpha / rank

// GEMM tiling
#define BM 128
#define BN 128
#define BK 32                  // fp32 elems per K chunk
#define NCHUNK (IN_DIM / BK)   // 128
#define STAGES 4
#define THREADS 256

#define SMEM_STRIDE 36                         // 32 + 4 pad floats per row
#define TILE_FLOATS (128 * SMEM_STRIDE)        // 4608 floats = 18432 B
#define STAGE_FLOATS (2 * TILE_FLOATS)         // A + B
#define SMEM_BYTES (STAGES * STAGE_FLOATS * 4) // 147456

#define TILES_M (M_ROWS / BM)   // 64
#define TILES_N (OUT_DIM / BN)  // 32
#define GROUP_M 8

// ============================================================================
// Scratch (device globals — no runtime allocation allowed)
// ============================================================================
__device__ __align__(1024) float g_weff[(size_t)OUT_DIM * IN_DIM];   // 64 MB
__device__ __align__(1024) float g_xr[(size_t)M_ROWS * IN_DIM];      // 128 MB

__constant__ float c_nf4[16] = {
    -1.0f, -0.6961928009986877f, -0.5250730514526367f, -0.39491748809814453f,
    -0.28444138169288635f, -0.18477343022823334f, -0.09105003625154495f, 0.0f,
    0.07958029955625534f, 0.16093020141124725f, 0.24611230194568634f,
    0.33791524171829224f, 0.44070982933044434f, 0.5626170039176941f,
    0.7229568362236328f, 1.0f};

// ============================================================================
// PTX helpers (baseline compute_100 features only: cp.async + mma.sync)
// ============================================================================
__device__ __forceinline__ uint32_t smem_u32(const void* p) {
    uint32_t a;
    asm("{ .reg .u64 t; cvta.to.shared.u64 t, %1; cvt.u32.u64 %0, t; }" : "=r"(a) : "l"(p));
    return a;
}
__device__ __forceinline__ float to_tf32(float f) {
    uint32_t u;
    asm("cvt.rna.tf32.f32 %0, %1;" : "=r"(u) : "f"(f));
    return __uint_as_float(u);
}
__device__ __forceinline__ void cp_async16(uint32_t saddr, const void* gptr) {
    asm volatile("cp.async.cg.shared.global [%0], [%1], 16;" :: "r"(saddr), "l"(gptr) : "memory");
}
#define CP_COMMIT() asm volatile("cp.async.commit_group;" ::: "memory")
#define CP_WAIT(n)  asm volatile("cp.async.wait_group %0;" :: "n"(n) : "memory")

__device__ __forceinline__ void mma_tf32(float& d0, float& d1, float& d2, float& d3,
                                         uint32_t a0, uint32_t a1, uint32_t a2, uint32_t a3,
                                         uint32_t b0, uint32_t b1) {
    asm volatile(
        "mma.sync.aligned.m16n8k8.row.col.f32.tf32.tf32.f32 "
        "{%0,%1,%2,%3}, {%4,%5,%6,%7}, {%8,%9}, {%0,%1,%2,%3};"
        : "+f"(d0), "+f"(d1), "+f"(d2), "+f"(d3)
        : "r"(a0), "r"(a1), "r"(a2), "r"(a3), "r"(b0), "r"(b1));
}

// ============================================================================
// Prep kernels
// ============================================================================
// W_eff[o][i] = nf4[code]*scale + 2.0 * sum_r lb[o][r]*la[r][i], rounded RNA->tf32
__global__ void prep_w_kernel(const int* __restrict__ codes,
                              const float* __restrict__ scales,
                              const float* __restrict__ la,
                              const float* __restrict__ lb,
                              float* __restrict__ weff) {
    int i = blockIdx.x * 256 + threadIdx.x;
    int o = blockIdx.y;
    const float* lbr = lb + o * RANK;
    float acc = 0.0f;
#pragma unroll
    for (int r = 0; r < RANK; r++)
        acc = fmaf(lbr[r], __ldg(la + r * IN_DIM + i), acc);
    float w = c_nf4[codes[(size_t)o * IN_DIM + i] & 15] * scales[o * (IN_DIM / BLOCK_Q) + (i >> 6)]
            + LORA_SCALE * acc;
    weff[(size_t)o * IN_DIM + i] = to_tf32(w);
}

// x -> tf32-rounded copy (RNA; truncation inside HMMA would bias the K=4096 sum)
__global__ void prep_x_kernel(const float4* __restrict__ in, float4* __restrict__ out) {
    int i = blockIdx.x * 256 + threadIdx.x;
    float4 v = in[i];
    v.x = to_tf32(v.x); v.y = to_tf32(v.y); v.z = to_tf32(v.z); v.w = to_tf32(v.w);
    out[i] = v;
}

// ============================================================================
// GEMM: out[M, N] = Xr[M, K] @ Weff[N, K]^T   (mma.sync tf32, fp32 accum)
// ============================================================================
__global__ void __launch_bounds__(THREADS, 1) gemm_tf32_kernel(
    const float* __restrict__ A,   // Xr [M, K]
    const float* __restrict__ B,   // Weff [N, K]
    float* __restrict__ out) {
    extern __shared__ float smem[];
    const int tid  = threadIdx.x;
    const int wid  = tid >> 5;
    const int lane = tid & 31;
    const int gid  = lane >> 2;   // group of 4
    const int tig  = lane & 3;    // thread in group

    // tile swizzle for L2 reuse
    const int bid   = blockIdx.x;
    const int group = bid / (GROUP_M * TILES_N);
    const int inb   = bid % (GROUP_M * TILES_N);
    const int mtile = group * GROUP_M + (inb % GROUP_M);
    const int ntile = inb / GROUP_M;
    const int m0 = mtile * BM;
    const int n0 = ntile * BN;

    const int wm = (wid & 1) * 64;   // warp M offset within CTA tile
    const int wn = (wid >> 1) * 32;  // warp N offset

    const uint32_t sbase = smem_u32(smem);

    // per-thread cp.async source/dest precompute: 8 segments (4 A + 4 B)
    // segment s covers row = idx/8, 16B chunk seg = idx%8 of the 128x32 tile
    const float* agp[4];
    const float* bgp[4];
    uint32_t asp[4], bsp[4];
#pragma unroll
    for (int i = 0; i < 4; i++) {
        int idx = tid + i * THREADS;          // 0..1023
        int row = idx >> 3;
        int seg = idx & 7;
        agp[i] = A + (size_t)(m0 + row) * IN_DIM + seg * 4;
        bgp[i] = B + (size_t)(n0 + row) * IN_DIM + seg * 4;
        asp[i] = sbase + (row * SMEM_STRIDE + seg * 4) * 4;
        bsp[i] = sbase + (TILE_FLOATS + row * SMEM_STRIDE + seg * 4) * 4;
    }

    float acc[4][4][4];
#pragma unroll
    for (int mt = 0; mt < 4; mt++)
#pragma unroll
        for (int nt = 0; nt < 4; nt++)
#pragma unroll
            for (int r = 0; r < 4; r++) acc[mt][nt][r] = 0.0f;

    // prologue: fill stages 0..STAGES-2
#pragma unroll
    for (int s = 0; s < STAGES - 1; s++) {
        uint32_t so = (uint32_t)(s * STAGE_FLOATS * 4);
#pragma unroll
        for (int i = 0; i < 4; i++) {
            cp_async16(asp[i] + so, agp[i] + s * BK);
            cp_async16(bsp[i] + so, bgp[i] + s * BK);
        }
        CP_COMMIT();
    }

    // mainloop
    for (int c = 0; c < NCHUNK; c++) {
        // issue load for chunk c+STAGES-1 into buffer (c+STAGES-1)%STAGES
        {
            int cl = c + STAGES - 1;
            if (cl < NCHUNK) {
                uint32_t so = (uint32_t)((cl % STAGES) * STAGE_FLOATS * 4);
#pragma unroll
                for (int i = 0; i < 4; i++) {
                    cp_async16(asp[i] + so, agp[i] + cl * BK);
                    cp_async16(bsp[i] + so, bgp[i] + cl * BK);
                }
            }
            CP_COMMIT();
        }
        CP_WAIT(STAGES - 2);       // chunk c's data resident
        __syncthreads();

        const float* As = smem + (c % STAGES) * STAGE_FLOATS;
        const float* Bs = As + TILE_FLOATS;

#pragma unroll
        for (int ks = 0; ks < BK / 8; ks++) {
            const int k0 = ks * 8;
            uint32_t a_frag[4][4];
            uint32_t b_frag[4][2];
#pragma unroll
            for (int mt = 0; mt < 4; mt++) {
                const float* ar = As + (wm + mt * 16 + gid) * SMEM_STRIDE + k0 + tig;
                a_frag[mt][0] = __float_as_uint(ar[0]);
                a_frag[mt][1] = __float_as_uint(ar[8 * SMEM_STRIDE]);
                a_frag[mt][2] = __float_as_uint(ar[4]);
                a_frag[mt][3] = __float_as_uint(ar[8 * SMEM_STRIDE + 4]);
            }
#pragma unroll
            for (int nt = 0; nt < 4; nt++) {
                const float* br = Bs + (wn + nt * 8 + gid) * SMEM_STRIDE + k0 + tig;
                b_frag[nt][0] = __float_as_uint(br[0]);
                b_frag[nt][1] = __float_as_uint(br[4]);
            }
#pragma unroll
            for (int mt = 0; mt < 4; mt++)
#pragma unroll
                for (int nt = 0; nt < 4; nt++)
                    mma_tf32(acc[mt][nt][0], acc[mt][nt][1], acc[mt][nt][2], acc[mt][nt][3],
                             a_frag[mt][0], a_frag[mt][1], a_frag[mt][2], a_frag[mt][3],
                             b_frag[nt][0], b_frag[nt][1]);
        }
        __syncthreads();   // protect buffer c%STAGES before iteration c+1 overwrites
    }

    // epilogue: D[row][col], row = m0+wm+mt*16+gid(+8), col = n0+wn+nt*8+tig*2(+1)
#pragma unroll
    for (int mt = 0; mt < 4; mt++) {
        const size_t r0 = (size_t)(m0 + wm + mt * 16 + gid) * OUT_DIM;
        const size_t r1 = r0 + 8 * OUT_DIM;
#pragma unroll
        for (int nt = 0; nt < 4; nt++) {
            const int col = n0 + wn + nt * 8 + tig * 2;
            float2 v0 = make_float2(acc[mt][nt][0], acc[mt][nt][1]);
            float2 v1 = make_float2(acc[mt][nt][2], acc[mt][nt][3]);
            *reinterpret_cast<float2*>(out + r0 + col) = v0;
            *reinterpret_cast<float2*>(out + r1 + col) = v1;
        }
    }
}

// ============================================================================
// Host
// ============================================================================
extern "C" void kernel_launch(void* const* d_in, const int* in_sizes, int n_in,
                              void* d_out, int out_size) {
    const float* x      = (const float*)d_in[0];
    const int*   codes  = (const int*)d_in[1];
    const float* scales = (const float*)d_in[2];
    const float* la     = (const float*)d_in[3];
    const float* lb     = (const float*)d_in[4];
    float* out = (float*)d_out;

    void *wptr = nullptr, *xptr = nullptr;
    cudaGetSymbolAddress(&wptr, g_weff);
    cudaGetSymbolAddress(&xptr, g_xr);

    // 1) fold LoRA + NF4 dequant into W_eff (tf32-rounded)
    prep_w_kernel<<<dim3(IN_DIM / 256, OUT_DIM), 256>>>(codes, scales, la, lb, (float*)wptr);
    // 2) tf32-round x into scratch
    prep_x_kernel<<<(M_ROWS * IN_DIM / 4) / 256, 256>>>((const float4*)x, (float4*)xptr);

    // 3) single large GEMM
    static bool attr_set = false;
    if (!attr_set) {
        cudaFuncSetAttribute(gemm_tf32_kernel,
                             cudaFuncAttributeMaxDynamicSharedMemorySize, SMEM_BYTES);
        attr_set = true;
    }
    gemm_tf32_kernel<<<TILES_M * TILES_N, THREADS, SMEM_BYTES>>>(
        (const float*)xptr, (const float*)wptr, out);
}

// round 3
// speedup vs baseline: 2.4050x; 2.4050x over previous
#include <cuda_runtime.h>
#include <cuda_fp16.h>
#include <cstdint>

// ============================================================================
// Problem constants
// ============================================================================
#define IN_DIM   4096
#define OUT_DIM  4096
#define M_ROWS   8192          // 4 * 2048
#define RANK     16
#define BLOCK_Q  64            // NF4 block size
#define LORA_SCALE 2.0f        // alpha / rank

// GEMM tiling (fp16 operands, fp32 accum)
#define BM 128
#define BN 128
#define BKH 64                 // halves per K chunk (= 128 B per row)
#define NCHUNK (IN_DIM / BKH)  // 64
#define STAGES 4
#define THREADS 256

#define TILE_BYTES (128 * 128)             // 16384 B per operand tile (128 rows x 128 B)
#define STAGE_BYTES (2 * TILE_BYTES)       // 32768
#define SMEM_BYTES (STAGES * STAGE_BYTES)  // 131072

#define TILES_M (M_ROWS / BM)   // 64
#define TILES_N (OUT_DIM / BN)  // 32
#define GROUP_M 8

// ============================================================================
// Scratch (device globals — no runtime allocation allowed)
// ============================================================================
__device__ __align__(1024) __half g_wh[(size_t)OUT_DIM * IN_DIM];   // 32 MB
__device__ __align__(1024) __half g_xh[(size_t)M_ROWS * IN_DIM];    // 64 MB

__constant__ float c_nf4[16] = {
    -1.0f, -0.6961928009986877f, -0.5250730514526367f, -0.39491748809814453f,
    -0.28444138169288635f, -0.18477343022823334f, -0.09105003625154495f, 0.0f,
    0.07958029955625534f, 0.16093020141124725f, 0.24611230194568634f,
    0.33791524171829224f, 0.44070982933044434f, 0.5626170039176941f,
    0.7229568362236328f, 1.0f};

// ============================================================================
// PTX helpers (baseline features only: cp.async, ldmatrix, mma.sync)
// ============================================================================
__device__ __forceinline__ uint32_t smem_u32(const void* p) {
    uint32_t a;
    asm("{ .reg .u64 t; cvta.to.shared.u64 t, %1; cvt.u32.u64 %0, t; }" : "=r"(a) : "l"(p));
    return a;
}
__device__ __forceinline__ void cp_async16(uint32_t saddr, const void* gptr) {
    asm volatile("cp.async.cg.shared.global [%0], [%1], 16;" :: "r"(saddr), "l"(gptr) : "memory");
}
#define CP_COMMIT() asm volatile("cp.async.commit_group;" ::: "memory")
#define CP_WAIT(n)  asm volatile("cp.async.wait_group %0;" :: "n"(n) : "memory")

#define LDSM_X4(r0, r1, r2, r3, addr)                                         \
    asm volatile("ldmatrix.sync.aligned.m8n8.x4.shared.b16 {%0,%1,%2,%3}, [%4];" \
        : "=r"(r0), "=r"(r1), "=r"(r2), "=r"(r3) : "r"(addr))

__device__ __forceinline__ void mma_fp16(float& d0, float& d1, float& d2, float& d3,
                                         uint32_t a0, uint32_t a1, uint32_t a2, uint32_t a3,
                                         uint32_t b0, uint32_t b1) {
    asm volatile(
        "mma.sync.aligned.m16n8k16.row.col.f32.f16.f16.f32 "
        "{%0,%1,%2,%3}, {%4,%5,%6,%7}, {%8,%9}, {%0,%1,%2,%3};"
        : "+f"(d0), "+f"(d1), "+f"(d2), "+f"(d3)
        : "r"(a0), "r"(a1), "r"(a2), "r"(a3), "r"(b0), "r"(b1));
}

// ============================================================================
// Prep kernels
// ============================================================================
// W_eff[o][i] = nf4[code]*scale + 2 * sum_r lb[o][r]*la[r][i]  -> fp16
// Block: 256 columns x 32 output rows; la/lb cached in smem.
__global__ void __launch_bounds__(256) prep_w_kernel(
    const int* __restrict__ codes, const float* __restrict__ scales,
    const float* __restrict__ la, const float* __restrict__ lb,
    __half* __restrict__ wh) {
    __shared__ float la_s[RANK][256];
    __shared__ float lb_s[32][RANK];
    const int t  = threadIdx.x;
    const int i0 = blockIdx.x * 256;
    const int o0 = blockIdx.y * 32;
#pragma unroll
    for (int r = 0; r < RANK; r++)
        la_s[r][t] = la[r * IN_DIM + i0 + t];
    for (int j = t; j < 32 * RANK; j += 256)
        lb_s[j >> 4][j & 15] = lb[(size_t)(o0 + (j >> 4)) * RANK + (j & 15)];
    __syncthreads();
    const int i = i0 + t;
#pragma unroll 4
    for (int oo = 0; oo < 32; oo++) {
        const int o = o0 + oo;
        float acc = 0.0f;
#pragma unroll
        for (int r = 0; r < RANK; r++)
            acc = fmaf(lb_s[oo][r], la_s[r][t], acc);
        float w = c_nf4[codes[(size_t)o * IN_DIM + i] & 15]
                    * scales[o * (IN_DIM / BLOCK_Q) + (i >> 6)]
                + LORA_SCALE * acc;
        wh[(size_t)o * IN_DIM + i] = __float2half_rn(w);
    }
}

// x (fp32) -> fp16
__global__ void prep_x_kernel(const float4* __restrict__ in, uint2* __restrict__ out) {
    int i = blockIdx.x * 256 + threadIdx.x;
    float4 v = in[i];
    __half2 h0 = __floats2half2_rn(v.x, v.y);
    __half2 h1 = __floats2half2_rn(v.z, v.w);
    uint2 u;
    u.x = *reinterpret_cast<uint32_t*>(&h0);
    u.y = *reinterpret_cast<uint32_t*>(&h1);
    out[i] = u;
}

// ============================================================================
// GEMM: out[M, N] = Xh[M, K] @ Wh[N, K]^T   (mma.sync fp16, fp32 accum)
// smem layout per tile: 128 rows x 128 B; 16B chunk c of row r stored at
// chunk (c ^ (r & 7)) — conflict-free for both cp.async and ldmatrix.
// ============================================================================
__global__ void __launch_bounds__(THREADS, 1) gemm_fp16_kernel(
    const __half* __restrict__ A,   // Xh [M, K]
    const __half* __restrict__ B,   // Wh [N, K]
    float* __restrict__ out) {
    extern __shared__ char smem[];
    const uint32_t sbase = smem_u32(smem);
    const int tid  = threadIdx.x;
    const int wid  = tid >> 5;
    const int lane = tid & 31;
    const int gid  = lane >> 2;
    const int tig  = lane & 3;

    // tile swizzle for L2 reuse
    const int bid   = blockIdx.x;
    const int group = bid / (GROUP_M * TILES_N);
    const int inb   = bid % (GROUP_M * TILES_N);
    const int mtile = group * GROUP_M + (inb % GROUP_M);
    const int ntile = inb / GROUP_M;
    const int m0 = mtile * BM;
    const int n0 = ntile * BN;

    const int wm = (wid & 1) * 64;   // warp M offset
    const int wn = (wid >> 1) * 32;  // warp N offset

    // cp.async per-thread segments: 4 for A + 4 for B
    const char* agp[4];
    const char* bgp[4];
    uint32_t asp[4], bsp[4];
#pragma unroll
    for (int i = 0; i < 4; i++) {
        int idx = tid + i * THREADS;   // 0..1023
        int row = idx >> 3;            // 0..127
        int seg = idx & 7;             // 16B chunk within 128B row
        agp[i] = (const char*)A + ((size_t)(m0 + row) * IN_DIM + seg * 8) * 2;
        bgp[i] = (const char*)B + ((size_t)(n0 + row) * IN_DIM + seg * 8) * 2;
        uint32_t so = (uint32_t)(row * 128 + ((seg ^ (row & 7)) * 16));
        asp[i] = sbase + so;
        bsp[i] = sbase + TILE_BYTES + so;
    }

    // ldmatrix address precompute (offsets within a tile)
    // A x4 at (r0 = wm+mt*16, k0 = ks*16): lane -> row r0+(lane&15), 16B chunk ks*2+(lane>>4)
    uint32_t a_off[4], a_x[4];
#pragma unroll
    for (int mt = 0; mt < 4; mt++) {
        int r = wm + mt * 16 + (lane & 15);
        a_off[mt] = (uint32_t)(r * 128);
        a_x[mt]   = (uint32_t)(r & 7);
    }
    const uint32_t a_hi = (uint32_t)(lane >> 4);
    // B x4 covering 16 n-rows (two 8-wide n tiles):
    // lane -> row wn+ntp*16+(lane&7)+((lane>>4)<<3), 16B chunk ks*2+((lane>>3)&1)
    uint32_t b_off[2], b_x[2];
#pragma unroll
    for (int ntp = 0; ntp < 2; ntp++) {
        int r = wn + ntp * 16 + (lane & 7) + ((lane >> 4) << 3);
        b_off[ntp] = (uint32_t)(r * 128);
        b_x[ntp]   = (uint32_t)(r & 7);
    }
    const uint32_t b_hi = (uint32_t)((lane >> 3) & 1);

    float acc[4][4][4];
#pragma unroll
    for (int mt = 0; mt < 4; mt++)
#pragma unroll
        for (int nt = 0; nt < 4; nt++)
#pragma unroll
            for (int r = 0; r < 4; r++) acc[mt][nt][r] = 0.0f;

    // prologue: fill stages 0..STAGES-2
#pragma unroll
    for (int s = 0; s < STAGES - 1; s++) {
        uint32_t so = (uint32_t)(s * STAGE_BYTES);
#pragma unroll
        for (int i = 0; i < 4; i++) {
            cp_async16(asp[i] + so, agp[i] + s * 128);
            cp_async16(bsp[i] + so, bgp[i] + s * 128);
        }
        CP_COMMIT();
    }

    // mainloop
    for (int c = 0; c < NCHUNK; c++) {
        {
            int cl = c + STAGES - 1;
            if (cl < NCHUNK) {
                uint32_t so = (uint32_t)((cl % STAGES) * STAGE_BYTES);
#pragma unroll
                for (int i = 0; i < 4; i++) {
                    cp_async16(asp[i] + so, agp[i] + cl * 128);
                    cp_async16(bsp[i] + so, bgp[i] + cl * 128);
                }
            }
            CP_COMMIT();
        }
        CP_WAIT(STAGES - 2);
        __syncthreads();

        const uint32_t As = sbase + (uint32_t)((c % STAGES) * STAGE_BYTES);
        const uint32_t Bs = As + TILE_BYTES;

#pragma unroll
        for (int ks = 0; ks < BKH / 16; ks++) {
            uint32_t a_frag[4][4];
            uint32_t b_frag[4][2];
#pragma unroll
            for (int mt = 0; mt < 4; mt++) {
                uint32_t ad = As + a_off[mt] + (((2u * ks + a_hi) ^ a_x[mt]) * 16);
                LDSM_X4(a_frag[mt][0], a_frag[mt][1], a_frag[mt][2], a_frag[mt][3], ad);
            }
#pragma unroll
            for (int ntp = 0; ntp < 2; ntp++) {
                uint32_t bd = Bs + b_off[ntp] + (((2u * ks + b_hi) ^ b_x[ntp]) * 16);
                LDSM_X4(b_frag[2 * ntp][0], b_frag[2 * ntp][1],
                        b_frag[2 * ntp + 1][0], b_frag[2 * ntp + 1][1], bd);
            }
#pragma unroll
            for (int mt = 0; mt < 4; mt++)
#pragma unroll
                for (int nt = 0; nt < 4; nt++)
                    mma_fp16(acc[mt][nt][0], acc[mt][nt][1], acc[mt][nt][2], acc[mt][nt][3],
                             a_frag[mt][0], a_frag[mt][1], a_frag[mt][2], a_frag[mt][3],
                             b_frag[nt][0], b_frag[nt][1]);
        }
        __syncthreads();
    }

    // epilogue: row = m0+wm+mt*16+gid(+8), col = n0+wn+nt*8+tig*2(+1)
#pragma unroll
    for (int mt = 0; mt < 4; mt++) {
        const size_t r0 = (size_t)(m0 + wm + mt * 16 + gid) * OUT_DIM;
        const size_t r1 = r0 + 8 * OUT_DIM;
#pragma unroll
        for (int nt = 0; nt < 4; nt++) {
            const int col = n0 + wn + nt * 8 + tig * 2;
            *reinterpret_cast<float2*>(out + r0 + col) =
                make_float2(acc[mt][nt][0], acc[mt][nt][1]);
            *reinterpret_cast<float2*>(out + r1 + col) =
                make_float2(acc[mt][nt][2], acc[mt][nt][3]);
        }
    }
}

// ============================================================================
// Host
// ============================================================================
extern "C" void kernel_launch(void* const* d_in, const int* in_sizes, int n_in,
                              void* d_out, int out_size) {
    const float* x      = (const float*)d_in[0];
    const int*   codes  = (const int*)d_in[1];
    const float* scales = (const float*)d_in[2];
    const float* la     = (const float*)d_in[3];
    const float* lb     = (const float*)d_in[4];
    float* out = (float*)d_out;

    void *wptr = nullptr, *xptr = nullptr;
    cudaGetSymbolAddress(&wptr, g_wh);
    cudaGetSymbolAddress(&xptr, g_xh);

    // 1) fold LoRA + NF4 dequant into W_eff (fp16)
    prep_w_kernel<<<dim3(IN_DIM / 256, OUT_DIM / 32), 256>>>(
        codes, scales, la, lb, (__half*)wptr);
    // 2) x -> fp16
    prep_x_kernel<<<(M_ROWS * IN_DIM / 4) / 256, 256>>>(
        (const float4*)x, (uint2*)xptr);

    // 3) single large GEMM
    static bool attr_set = false;
    if (!attr_set) {
        cudaFuncSetAttribute(gemm_fp16_kernel,
                             cudaFuncAttributeMaxDynamicSharedMemorySize, SMEM_BYTES);
        attr_set = true;
    }
    gemm_fp16_kernel<<<TILES_M * TILES_N, THREADS, SMEM_BYTES>>>(
        (const __half*)xptr, (const __half*)wptr, out);
}

// round 4
// speedup vs baseline: 2.7874x; 1.1590x over previous
#include <cuda_runtime.h>
#include <cuda_fp16.h>
#include <cstdint>

// ============================================================================
// Problem constants
// ============================================================================
#define IN_DIM   4096
#define OUT_DIM  4096
#define M_ROWS   8192          // 4 * 2048
#define RANK     16
#define BLOCK_Q  64            // NF4 block size
#define LORA_SCALE 2.0f        // alpha / rank

// GEMM tiling (fp16 operands, fp32 accum)
#define BM 256
#define BN 128
#define BKH 64                 // halves per K chunk (= 128 B per row)
#define NCHUNK (IN_DIM / BKH)  // 64
#define STAGES 4
#define THREADS 512

#define A_TILE_BYTES (BM * 128)                 // 32768
#define B_TILE_BYTES (BN * 128)                 // 16384
#define STAGE_BYTES (A_TILE_BYTES + B_TILE_BYTES)  // 49152
#define SMEM_BYTES (STAGES * STAGE_BYTES)       // 196608

#define TILES_M (M_ROWS / BM)   // 32
#define TILES_N (OUT_DIM / BN)  // 32
#define GROUP_M 8

// ============================================================================
// Scratch (device globals — no runtime allocation allowed)
// ============================================================================
__device__ __align__(1024) __half g_wh[(size_t)OUT_DIM * IN_DIM];   // 32 MB
__device__ __align__(1024) __half g_xh[(size_t)M_ROWS * IN_DIM];    // 64 MB

__constant__ float c_nf4[16] = {
    -1.0f, -0.6961928009986877f, -0.5250730514526367f, -0.39491748809814453f,
    -0.28444138169288635f, -0.18477343022823334f, -0.09105003625154495f, 0.0f,
    0.07958029955625534f, 0.16093020141124725f, 0.24611230194568634f,
    0.33791524171829224f, 0.44070982933044434f, 0.5626170039176941f,
    0.7229568362236328f, 1.0f};

// ============================================================================
// PTX helpers (baseline features only: cp.async, ldmatrix, mma.sync)
// ============================================================================
__device__ __forceinline__ uint32_t smem_u32(const void* p) {
    uint32_t a;
    asm("{ .reg .u64 t; cvta.to.shared.u64 t, %1; cvt.u32.u64 %0, t; }" : "=r"(a) : "l"(p));
    return a;
}
__device__ __forceinline__ void cp_async16(uint32_t saddr, const void* gptr) {
    asm volatile("cp.async.cg.shared.global [%0], [%1], 16;" :: "r"(saddr), "l"(gptr) : "memory");
}
#define CP_COMMIT() asm volatile("cp.async.commit_group;" ::: "memory")
#define CP_WAIT(n)  asm volatile("cp.async.wait_group %0;" :: "n"(n) : "memory")

#define LDSM_X4(r0, r1, r2, r3, addr)                                         \
    asm volatile("ldmatrix.sync.aligned.m8n8.x4.shared.b16 {%0,%1,%2,%3}, [%4];" \
        : "=r"(r0), "=r"(r1), "=r"(r2), "=r"(r3) : "r"(addr))

__device__ __forceinline__ void mma_fp16(float& d0, float& d1, float& d2, float& d3,
                                         uint32_t a0, uint32_t a1, uint32_t a2, uint32_t a3,
                                         uint32_t b0, uint32_t b1) {
    asm volatile(
        "mma.sync.aligned.m16n8k16.row.col.f32.f16.f16.f32 "
        "{%0,%1,%2,%3}, {%4,%5,%6,%7}, {%8,%9}, {%0,%1,%2,%3};"
        : "+f"(d0), "+f"(d1), "+f"(d2), "+f"(d3)
        : "r"(a0), "r"(a1), "r"(a2), "r"(a3), "r"(b0), "r"(b1));
}

// ============================================================================
// Prep kernels
// ============================================================================
// W_eff[o][i] = nf4[code]*scale + 2 * sum_r lb[o][r]*la[r][i]  -> fp16
// Block: 1024 columns (4 per thread) x 32 output rows. la rows cached in
// registers as float4 after one smem staging pass; nf4 table in smem.
__global__ void __launch_bounds__(256) prep_w_kernel(
    const int* __restrict__ codes, const float* __restrict__ scales,
    const float* __restrict__ la, const float* __restrict__ lb,
    __half* __restrict__ wh) {
    extern __shared__ float la_s[];         // [16][1024]
    __shared__ float lb_s[32][RANK];
    __shared__ float nf4_s[16];
    const int t  = threadIdx.x;
    const int i0 = blockIdx.x * 1024;
    const int o0 = blockIdx.y * 32;
    if (t < 16) nf4_s[t] = c_nf4[t];
#pragma unroll
    for (int r = 0; r < RANK; r++)
        reinterpret_cast<float4*>(la_s)[r * 256 + t] =
            reinterpret_cast<const float4*>(la + r * IN_DIM + i0)[t];
    for (int j = t; j < 32 * RANK; j += 256)
        lb_s[j >> 4][j & 15] = lb[(size_t)(o0 + (j >> 4)) * RANK + (j & 15)];
    __syncthreads();

    float4 a4[RANK];
#pragma unroll
    for (int r = 0; r < RANK; r++)
        a4[r] = reinterpret_cast<const float4*>(la_s)[r * 256 + t];

    const int i = i0 + 4 * t;
#pragma unroll 2
    for (int oo = 0; oo < 32; oo++) {
        const int o = o0 + oo;
        const int4 cd = *reinterpret_cast<const int4*>(codes + (size_t)o * IN_DIM + i);
        const float s = scales[o * (IN_DIM / BLOCK_Q) + (i >> 6)];
        float ax = 0.f, ay = 0.f, az = 0.f, aw = 0.f;
#pragma unroll
        for (int r = 0; r < RANK; r++) {
            const float b = lb_s[oo][r];
            ax = fmaf(b, a4[r].x, ax);
            ay = fmaf(b, a4[r].y, ay);
            az = fmaf(b, a4[r].z, az);
            aw = fmaf(b, a4[r].w, aw);
        }
        const float wx = fmaf(nf4_s[cd.x & 15], s, LORA_SCALE * ax);
        const float wy = fmaf(nf4_s[cd.y & 15], s, LORA_SCALE * ay);
        const float wz = fmaf(nf4_s[cd.z & 15], s, LORA_SCALE * az);
        const float ww = fmaf(nf4_s[cd.w & 15], s, LORA_SCALE * aw);
        __half2 h0 = __floats2half2_rn(wx, wy);
        __half2 h1 = __floats2half2_rn(wz, ww);
        uint2 u;
        u.x = *reinterpret_cast<uint32_t*>(&h0);
        u.y = *reinterpret_cast<uint32_t*>(&h1);
        *reinterpret_cast<uint2*>(wh + (size_t)o * IN_DIM + i) = u;
    }
}

// x (fp32) -> fp16
__global__ void prep_x_kernel(const float4* __restrict__ in, uint2* __restrict__ out) {
    int i = blockIdx.x * 256 + threadIdx.x;
    float4 v = in[i];
    __half2 h0 = __floats2half2_rn(v.x, v.y);
    __half2 h1 = __floats2half2_rn(v.z, v.w);
    uint2 u;
    u.x = *reinterpret_cast<uint32_t*>(&h0);
    u.y = *reinterpret_cast<uint32_t*>(&h1);
    out[i] = u;
}

// ============================================================================
// GEMM: out[M, N] = Xh[M, K] @ Wh[N, K]^T   (mma.sync fp16, fp32 accum)
// BM=256 x BN=128, 512 threads (16 warps = 4/SMSP), warp tile 64x32.
// smem tile: rows x 128 B; 16B chunk c of row r stored at chunk (c ^ (r & 7)).
// Single __syncthreads per chunk (CUTLASS multistage ordering).
// ============================================================================
__global__ void __launch_bounds__(THREADS, 1) gemm_fp16_kernel(
    const __half* __restrict__ A,   // Xh [M, K]
    const __half* __restrict__ B,   // Wh [N, K]
    float* __restrict__ out) {
    extern __shared__ char smem[];
    const uint32_t sbase = smem_u32(smem);
    const int tid  = threadIdx.x;
    const int wid  = tid >> 5;
    const int lane = tid & 31;
    const int gid  = lane >> 2;
    const int tig  = lane & 3;

    // tile swizzle for L2 reuse
    const int bid   = blockIdx.x;
    const int group = bid / (GROUP_M * TILES_N);
    const int inb   = bid % (GROUP_M * TILES_N);
    const int mtile = group * GROUP_M + (inb % GROUP_M);
    const int ntile = inb / GROUP_M;
    const int m0 = mtile * BM;
    const int n0 = ntile * BN;

    const int wm = (wid & 3) * 64;   // warp M offset (4 warps along M)
    const int wn = (wid >> 2) * 32;  // warp N offset (4 warps along N)

    // cp.async per-thread segments: 4 for A (256 rows x 8 seg / 512 thr) + 2 for B
    const char* agp[4];
    const char* bgp[2];
    uint32_t asp[4], bsp[2];
#pragma unroll
    for (int i = 0; i < 4; i++) {
        int idx = tid + i * THREADS;   // 0..2047
        int row = idx >> 3;            // 0..255
        int seg = idx & 7;
        agp[i] = (const char*)A + ((size_t)(m0 + row) * IN_DIM + seg * 8) * 2;
        asp[i] = sbase + (uint32_t)(row * 128 + ((seg ^ (row & 7)) * 16));
    }
#pragma unroll
    for (int i = 0; i < 2; i++) {
        int idx = tid + i * THREADS;   // 0..1023
        int row = idx >> 3;            // 0..127
        int seg = idx & 7;
        bgp[i] = (const char*)B + ((size_t)(n0 + row) * IN_DIM + seg * 8) * 2;
        bsp[i] = sbase + A_TILE_BYTES + (uint32_t)(row * 128 + ((seg ^ (row & 7)) * 16));
    }

    // ldmatrix address precompute (offsets within a tile)
    uint32_t a_off[4], a_x[4];
#pragma unroll
    for (int mt = 0; mt < 4; mt++) {
        int r = wm + mt * 16 + (lane & 15);
        a_off[mt] = (uint32_t)(r * 128);
        a_x[mt]   = (uint32_t)(r & 7);
    }
    const uint32_t a_hi = (uint32_t)(lane >> 4);
    uint32_t b_off[2], b_x[2];
#pragma unroll
    for (int ntp = 0; ntp < 2; ntp++) {
        int r = wn + ntp * 16 + (lane & 7) + ((lane >> 4) << 3);
        b_off[ntp] = (uint32_t)(r * 128);
        b_x[ntp]   = (uint32_t)(r & 7);
    }
    const uint32_t b_hi = (uint32_t)((lane >> 3) & 1);

    float acc[4][4][4];
#pragma unroll
    for (int mt = 0; mt < 4; mt++)
#pragma unroll
        for (int nt = 0; nt < 4; nt++)
#pragma unroll
            for (int r = 0; r < 4; r++) acc[mt][nt][r] = 0.0f;

    // prologue: fill stages 0..STAGES-2 (chunks 0..2)
#pragma unroll
    for (int s = 0; s < STAGES - 1; s++) {
        uint32_t so = (uint32_t)(s * STAGE_BYTES);
#pragma unroll
        for (int i = 0; i < 4; i++) cp_async16(asp[i] + so, agp[i] + s * 128);
#pragma unroll
        for (int i = 0; i < 2; i++) cp_async16(bsp[i] + so, bgp[i] + s * 128);
        CP_COMMIT();
    }

    // mainloop — exactly one commit and one __syncthreads per chunk
    for (int c = 0; c < NCHUNK; c++) {
        CP_WAIT(STAGES - 2);       // chunk c resident
        __syncthreads();           // also proves all warps done reading buf (c-1)%S

        {   // issue chunk c+3 into buffer (c+3)%S (= (c-1)%S, now safe)
            int cl = c + STAGES - 1;
            if (cl < NCHUNK) {
                uint32_t so = (uint32_t)((cl % STAGES) * STAGE_BYTES);
#pragma unroll
                for (int i = 0; i < 4; i++) cp_async16(asp[i] + so, agp[i] + cl * 128);
#pragma unroll
                for (int i = 0; i < 2; i++) cp_async16(bsp[i] + so, bgp[i] + cl * 128);
            }
            CP_COMMIT();           // commit every iter (keeps wait_group counts aligned)
        }

        const uint32_t As = sbase + (uint32_t)((c % STAGES) * STAGE_BYTES);
        const uint32_t Bs = As + A_TILE_BYTES;

#pragma unroll
        for (int ks = 0; ks < BKH / 16; ks++) {
            uint32_t a_frag[4][4];
            uint32_t b_frag[4][2];
#pragma unroll
            for (int mt = 0; mt < 4; mt++) {
                uint32_t ad = As + a_off[mt] + (((2u * ks + a_hi) ^ a_x[mt]) * 16);
                LDSM_X4(a_frag[mt][0], a_frag[mt][1], a_frag[mt][2], a_frag[mt][3], ad);
            }
#pragma unroll
            for (int ntp = 0; ntp < 2; ntp++) {
                uint32_t bd = Bs + b_off[ntp] + (((2u * ks + b_hi) ^ b_x[ntp]) * 16);
                LDSM_X4(b_frag[2 * ntp][0], b_frag[2 * ntp][1],
                        b_frag[2 * ntp + 1][0], b_frag[2 * ntp + 1][1], bd);
            }
#pragma unroll
            for (int mt = 0; mt < 4; mt++)
#pragma unroll
                for (int nt = 0; nt < 4; nt++)
                    mma_fp16(acc[mt][nt][0], acc[mt][nt][1], acc[mt][nt][2], acc[mt][nt][3],
                             a_frag[mt][0], a_frag[mt][1], a_frag[mt][2], a_frag[mt][3],
                             b_frag[nt][0], b_frag[nt][1]);
        }
    }

    // epilogue: row = m0+wm+mt*16+gid(+8), col = n0+wn+nt*8+tig*2(+1)
#pragma unroll
    for (int mt = 0; mt < 4; mt++) {
        const size_t r0 = (size_t)(m0 + wm + mt * 16 + gid) * OUT_DIM;
        const size_t r1 = r0 + 8 * OUT_DIM;
#pragma unroll
        for (int nt = 0; nt < 4; nt++) {
            const int col = n0 + wn + nt * 8 + tig * 2;
            *reinterpret_cast<float2*>(out + r0 + col) =
                make_float2(acc[mt][nt][0], acc[mt][nt][1]);
            *reinterpret_cast<float2*>(out + r1 + col) =
                make_float2(acc[mt][nt][2], acc[mt][nt][3]);
        }
    }
}

// ============================================================================
// Host
// ============================================================================
extern "C" void kernel_launch(void* const* d_in, const int* in_sizes, int n_in,
                              void* d_out, int out_size) {
    const float* x      = (const float*)d_in[0];
    const int*   codes  = (const int*)d_in[1];
    const float* scales = (const float*)d_in[2];
    const float* la     = (const float*)d_in[3];
    const float* lb     = (const float*)d_in[4];
    float* out = (float*)d_out;

    void *wptr = nullptr, *xptr = nullptr;
    cudaGetSymbolAddress(&wptr, g_wh);
    cudaGetSymbolAddress(&xptr, g_xh);

    static bool attr_set = false;
    if (!attr_set) {
        cudaFuncSetAttribute(gemm_fp16_kernel,
                             cudaFuncAttributeMaxDynamicSharedMemorySize, SMEM_BYTES);
        cudaFuncSetAttribute(prep_w_kernel,
                             cudaFuncAttributeMaxDynamicSharedMemorySize, 65536);
        attr_set = true;
    }

    // 1) fold LoRA + NF4 dequant into W_eff (fp16)
    prep_w_kernel<<<dim3(IN_DIM / 1024, OUT_DIM / 32), 256, 65536>>>(
        codes, scales, la, lb, (__half*)wptr);
    // 2) x -> fp16
    prep_x_kernel<<<(M_ROWS * IN_DIM / 4) / 256, 256>>>(
        (const float4*)x, (uint2*)xptr);

    // 3) single large GEMM
    gemm_fp16_kernel<<<TILES_M * TILES_N, THREADS, SMEM_BYTES>>>(
        (const __half*)xptr, (const __half*)wptr, out);
}